// round 12
// baseline (speedup 1.0000x reference)
#include <cuda_runtime.h>
#include <cuda_bf16.h>
#include <math.h>

#define TT   512
#define BB   128
#define DIN  102
#define HH   256
#define G4   1024
#define DLIN 128
#define KK   9

// ---------------- device scratch ----------------
// gates layout: [dir][t][col][b]  (fp32)
__device__ float g_gates[(size_t)2 * TT * G4 * BB];
// h layout: bf16 [dir][slot][b][unit] (unit contiguous)
// fwd: slot t+1 = h(t), slot0 zeros; bwd: slot t = h(t), slot TT zeros
__device__ __nv_bfloat16 g_h16[(size_t)2 * (TT + 1) * BB * HH];
__device__ float g_em[(size_t)BB * TT * KK];
__device__ unsigned int g_bar8[8];

__device__ __forceinline__ float d2t(float x) {   // round-to-nearest tf32
    float r;
    asm("cvt.rna.tf32.f32 %0, %1;" : "=f"(r) : "f"(x));
    return r;
}
__device__ __forceinline__ unsigned pk2(float lo, float hi) {
    __nv_bfloat162 t = __floats2bfloat162_rn(lo, hi);
    return *(unsigned*)&t;
}
__device__ __forceinline__ void mma8(float* d, const float* a, float b0, float b1) {
    asm volatile(
        "mma.sync.aligned.m16n8k8.row.col.f32.tf32.tf32.f32 "
        "{%0,%1,%2,%3}, {%4,%5,%6,%7}, {%8,%9}, {%0,%1,%2,%3};\n"
        : "+f"(d[0]), "+f"(d[1]), "+f"(d[2]), "+f"(d[3])
        : "r"(__float_as_uint(a[0])), "r"(__float_as_uint(a[1])),
          "r"(__float_as_uint(a[2])), "r"(__float_as_uint(a[3])),
          "r"(__float_as_uint(b0)), "r"(__float_as_uint(b1)));
}
__device__ __forceinline__ void mma16(float* d, const unsigned* a,
                                      unsigned b0, unsigned b1) {
    asm volatile(
        "mma.sync.aligned.m16n8k16.row.col.f32.bf16.bf16.f32 "
        "{%0,%1,%2,%3}, {%4,%5,%6,%7}, {%8,%9}, {%0,%1,%2,%3};\n"
        : "+f"(d[0]), "+f"(d[1]), "+f"(d[2]), "+f"(d[3])
        : "r"(a[0]), "r"(a[1]), "r"(a[2]), "r"(a[3]),
          "r"(b0), "r"(b1));
}
__device__ __forceinline__ float sigf(float x)  { return 1.f / (1.f + __expf(-x)); }
__device__ __forceinline__ float tanhfx(float x){ return 2.f / (1.f + __expf(-2.f * x)) - 1.f; }
__device__ __forceinline__ void bar_release(unsigned int* p) {
    unsigned one = 1u;
    asm volatile("red.release.gpu.global.add.u32 [%0], %1;" :: "l"(p), "r"(one) : "memory");
}
__device__ __forceinline__ void bar_acquire_wait(unsigned int* p, unsigned target) {
    unsigned val;
    do {
        asm volatile("ld.acquire.gpu.global.u32 %0, [%1];" : "=r"(val) : "l"(p));
    } while (val < target);
}

// ---------------- kernel 0 ----------------
__global__ void k_zero(float* out) {
    int idx = blockIdx.x * blockDim.x + threadIdx.x;
    int stride = gridDim.x * blockDim.x;
    if (idx == 0) {
        #pragma unroll
        for (int i = 0; i < 8; ++i) g_bar8[i] = 0u;
        out[0] = 0.f;
    }
    const int HBW = BB * HH / 2;   // uints per slot
    unsigned* hf0 = (unsigned*)g_h16;                                        // dir0 slot0
    unsigned* hbT = (unsigned*)(g_h16 + (size_t)((TT + 1) + TT) * BB * HH);  // dir1 slotTT
    for (int i = idx; i < HBW; i += stride) { hf0[i] = 0u; hbT[i] = 0u; }
}

// ---------------- kernel 1: gates = x @ Wih^T + b  (tf32 mma) ------------
__global__ void __launch_bounds__(256) k_proj(
    const float* __restrict__ x,
    const float* __restrict__ Wih_f, const float* __restrict__ b_f,
    const float* __restrict__ Wih_b, const float* __restrict__ b_b)
{
    unsigned bx = blockIdx.x;
    int bh   = bx & 1;
    int colt = (bx >> 1) & 7;
    int t    = (bx >> 4) & 511;
    int dir  = bx >> 13;
    const float* Wih  = dir ? Wih_b : Wih_f;
    const float* bias = dir ? b_b : b_f;
    int col0 = colt * 128;
    int tid = threadIdx.x;
    int lane = tid & 31, w = tid >> 5;
    int q = lane >> 2, tg = lane & 3;
    int rowA = col0 + w * 16 + q;
    int rowB = rowA + 8;

    __shared__ float xs[104][72];

    float aF[13][4];
    #pragma unroll
    for (int kk = 0; kk < 13; ++kk) {
        int k = kk * 8 + tg;
        aF[kk][0] = (k < DIN)     ? d2t(Wih[(size_t)rowA * DIN + k])     : 0.f;
        aF[kk][1] = (k < DIN)     ? d2t(Wih[(size_t)rowB * DIN + k])     : 0.f;
        aF[kk][2] = (k + 4 < DIN) ? d2t(Wih[(size_t)rowA * DIN + k + 4]) : 0.f;
        aF[kk][3] = (k + 4 < DIN) ? d2t(Wih[(size_t)rowB * DIN + k + 4]) : 0.f;
    }
    for (int i = tid; i < 2 * 64; i += 256) xs[102 + (i >> 6)][i & 63] = 0.f;
    for (int f = tid; f < 64 * DIN; f += 256) {
        int b = f / DIN, d = f - b * DIN;
        xs[d][b] = d2t(x[((size_t)(bh * 64 + b) * TT + t) * DIN + d]);
    }
    __syncthreads();

    float acc[8][4];
    #pragma unroll
    for (int nt = 0; nt < 8; ++nt)
        #pragma unroll
        for (int j = 0; j < 4; ++j) acc[nt][j] = 0.f;

    #pragma unroll
    for (int kk = 0; kk < 13; ++kk) {
        #pragma unroll
        for (int nt = 0; nt < 8; ++nt) {
            float b0 = xs[kk * 8 + tg][nt * 8 + q];
            float b1 = xs[kk * 8 + tg + 4][nt * 8 + q];
            mma8(acc[nt], aF[kk], b0, b1);
        }
    }

    float bA = bias[rowA], bB = bias[rowB];
    float* gt = g_gates + ((size_t)(dir * TT + t)) * (G4 * BB);
    #pragma unroll
    for (int nt = 0; nt < 8; ++nt) {
        int cb = bh * 64 + nt * 8 + 2 * tg;
        *(float2*)&gt[(size_t)rowA * BB + cb] = make_float2(acc[nt][0] + bA, acc[nt][1] + bA);
        *(float2*)&gt[(size_t)rowB * BB + cb] = make_float2(acc[nt][2] + bB, acc[nt][3] + bB);
    }
}

// ---------------- kernel 2: persistent BiLSTM, dual-stream ---------------
// 128 CTAs = ug(32) x bq(4); 256 thr. Each CTA: 8 units x 32 batch for
// BOTH directions, interleaved so each dir's grid-barrier latency is
// hidden under the other dir's compute. 8 barriers (dir x bq), 32 arrivals.
__global__ void __launch_bounds__(256, 1) k_rnn(
    const float* __restrict__ Whh_f, const float* __restrict__ Whh_b)
{
    int tid  = threadIdx.x;
    int lane = tid & 31, w = tid >> 5;
    int mh = w >> 2;                  // 0..1: gate pair
    int ng = w & 3;                   // 0..3: 8-batch group
    int ug = blockIdx.x >> 2;         // 0..31
    int bq = blockIdx.x & 3;          // 0..3
    int u0 = ug * 8;
    int boff = bq * 32;

    __shared__ unsigned hsW[32 * 132];       // h tile [b32][k], bf16 pairs
    __shared__ float outs[32 * 36];          // [gate*8+u][b32]
    __shared__ float csh0[8 * 32], csh1[8 * 32];
    __shared__ __nv_bfloat16 hb[32][8];      // h out staging [b][u]

    int q  = lane >> 2;
    int tg = lane & 3;
    int rowA = (2 * mh) * 256 + u0 + q;
    int rowB = rowA + 256;

    // A fragments for both directions (64 regs each)
    unsigned aF0[16][4], aF1[16][4];
    {
        const float* WA0 = Whh_f + (size_t)rowA * HH;
        const float* WB0 = Whh_f + (size_t)rowB * HH;
        const float* WA1 = Whh_b + (size_t)rowA * HH;
        const float* WB1 = Whh_b + (size_t)rowB * HH;
        #pragma unroll
        for (int kk = 0; kk < 16; ++kk) {
            int k0 = kk * 16 + 2 * tg;
            float2 a;
            a = *(const float2*)&WA0[k0];     aF0[kk][0] = pk2(a.x, a.y);
            a = *(const float2*)&WB0[k0];     aF0[kk][1] = pk2(a.x, a.y);
            a = *(const float2*)&WA0[k0 + 8]; aF0[kk][2] = pk2(a.x, a.y);
            a = *(const float2*)&WB0[k0 + 8]; aF0[kk][3] = pk2(a.x, a.y);
            a = *(const float2*)&WA1[k0];     aF1[kk][0] = pk2(a.x, a.y);
            a = *(const float2*)&WB1[k0];     aF1[kk][1] = pk2(a.x, a.y);
            a = *(const float2*)&WA1[k0 + 8]; aF1[kk][2] = pk2(a.x, a.y);
            a = *(const float2*)&WB1[k0 + 8]; aF1[kk][3] = pk2(a.x, a.y);
        }
    }
    if (tid < 256) { csh0[tid] = 0.f; csh1[tid] = 0.f; }
    __syncthreads();

    const size_t HB = (size_t)BB * HH;
    __nv_bfloat16* h0 = g_h16;                          // dir0
    __nv_bfloat16* h1 = g_h16 + (size_t)(TT + 1) * HB;  // dir1
    const float* gbase0 = g_gates;
    const float* gbase1 = g_gates + (size_t)TT * (size_t)(G4 * BB);
    unsigned int* bar0 = &g_bar8[bq];
    unsigned int* bar1 = &g_bar8[4 + bq];
    int gcol = boff + ng * 8 + 2 * tg;

    // prefetch gates for first steps
    float2 gA0, gB0, gA1, gB1;
    gA0 = *(const float2*)&gbase0[(size_t)rowA * BB + gcol];
    gB0 = *(const float2*)&gbase0[(size_t)rowB * BB + gcol];
    {
        const float* gt = gbase1 + (size_t)(TT - 1) * (G4 * BB);
        gA1 = *(const float2*)&gt[(size_t)rowA * BB + gcol];
        gB1 = *(const float2*)&gt[(size_t)rowB * BB + gcol];
    }

    int brow = tid >> 3;      // 0..31 batch row
    int bc8  = tid & 7;       // 16B column index
    int eu = tid >> 5, ecc = tid & 31;    // epilogue mapping
    int bfrag = (ng * 8 + q) * 132 + tg;  // B-fragment base (per kk add 8*kk)

    for (int s = 0; s < TT; ++s) {
        // ===================== stream 0: fwd, t = s =====================
        {
            if (s) bar_acquire_wait(bar0, (unsigned)s * 32u);
            const __nv_bfloat16* hin = h0 + (size_t)s * HB + (size_t)boff * HH;
            #pragma unroll
            for (int i = 0; i < 4; ++i) {
                uint4 v = *(const uint4*)(hin + (size_t)brow * HH + (bc8 + 8 * i) * 8);
                *(uint4*)&hsW[brow * 132 + (bc8 + 8 * i) * 4] = v;
            }
            __syncthreads();

            float acc[4] = {gA0.x, gA0.y, gB0.x, gB0.y};
            #pragma unroll
            for (int kk = 0; kk < 16; ++kk) {
                int base = bfrag + kk * 8;
                mma16(acc, aF0[kk], hsW[base], hsW[base + 4]);
            }
            *(float2*)&outs[((2 * mh) * 8 + q) * 36 + ng * 8 + 2 * tg] =
                make_float2(acc[0], acc[1]);
            *(float2*)&outs[((2 * mh + 1) * 8 + q) * 36 + ng * 8 + 2 * tg] =
                make_float2(acc[2], acc[3]);
            __syncthreads();

            {
                float iv = outs[eu * 36 + ecc];
                float fv = outs[(8 + eu) * 36 + ecc];
                float gv = outs[(16 + eu) * 36 + ecc];
                float ov = outs[(24 + eu) * 36 + ecc];
                float c = sigf(fv) * csh0[eu * 32 + ecc] + sigf(iv) * tanhfx(gv);
                csh0[eu * 32 + ecc] = c;
                hb[ecc][eu] = __float2bfloat16_rn(sigf(ov) * tanhfx(c));
            }
            __syncthreads();
            if (tid < 32) {
                uint4 hv = *(uint4*)&hb[tid][0];
                *(uint4*)(h0 + (size_t)(s + 1) * HB + (size_t)(boff + tid) * HH + u0) = hv;
            }
            __syncthreads();
            if (tid == 0) bar_release(bar0);
            if (s + 1 < TT) {
                const float* gt = gbase0 + (size_t)(s + 1) * (G4 * BB);
                gA0 = *(const float2*)&gt[(size_t)rowA * BB + gcol];
                gB0 = *(const float2*)&gt[(size_t)rowB * BB + gcol];
            }
        }
        // ===================== stream 1: bwd, tb = TT-1-s ===============
        {
            int tb = TT - 1 - s;
            if (s) bar_acquire_wait(bar1, (unsigned)s * 32u);
            const __nv_bfloat16* hin = h1 + (size_t)(tb + 1) * HB + (size_t)boff * HH;
            #pragma unroll
            for (int i = 0; i < 4; ++i) {
                uint4 v = *(const uint4*)(hin + (size_t)brow * HH + (bc8 + 8 * i) * 8);
                *(uint4*)&hsW[brow * 132 + (bc8 + 8 * i) * 4] = v;
            }
            __syncthreads();

            float acc[4] = {gA1.x, gA1.y, gB1.x, gB1.y};
            #pragma unroll
            for (int kk = 0; kk < 16; ++kk) {
                int base = bfrag + kk * 8;
                mma16(acc, aF1[kk], hsW[base], hsW[base + 4]);
            }
            *(float2*)&outs[((2 * mh) * 8 + q) * 36 + ng * 8 + 2 * tg] =
                make_float2(acc[0], acc[1]);
            *(float2*)&outs[((2 * mh + 1) * 8 + q) * 36 + ng * 8 + 2 * tg] =
                make_float2(acc[2], acc[3]);
            __syncthreads();

            {
                float iv = outs[eu * 36 + ecc];
                float fv = outs[(8 + eu) * 36 + ecc];
                float gv = outs[(16 + eu) * 36 + ecc];
                float ov = outs[(24 + eu) * 36 + ecc];
                float c = sigf(fv) * csh1[eu * 32 + ecc] + sigf(iv) * tanhfx(gv);
                csh1[eu * 32 + ecc] = c;
                hb[ecc][eu] = __float2bfloat16_rn(sigf(ov) * tanhfx(c));
            }
            __syncthreads();
            if (tid < 32) {
                uint4 hv = *(uint4*)&hb[tid][0];
                *(uint4*)(h1 + (size_t)tb * HB + (size_t)(boff + tid) * HH + u0) = hv;
            }
            __syncthreads();
            if (tid == 0) bar_release(bar1);
            if (s + 1 < TT) {
                const float* gt = gbase1 + (size_t)(tb - 1) * (G4 * BB);
                gA1 = *(const float2*)&gt[(size_t)rowA * BB + gcol];
                gB1 = *(const float2*)&gt[(size_t)rowB * BB + gcol];
            }
        }
    }
}

// ---------------- kernel 3: feats + emissions (bf16 mma) -----------------
__global__ void __launch_bounds__(256) k_feats(
    const float* __restrict__ Wlin, const float* __restrict__ blin,
    const float* __restrict__ Wcls, const float* __restrict__ bcls)
{
    unsigned bx = blockIdx.x;
    int bh = bx & 1;
    int t  = bx >> 1;
    int tid = threadIdx.x;
    int lane = tid & 31, w = tid >> 5;
    int q = lane >> 2, tg = lane & 3;

    __shared__ float smem[9616];
    unsigned* hsW = (unsigned*)smem;          // phase1: [64 b][36w] h chunk
    unsigned* Ws2 = (unsigned*)(smem + 2304); // phase1: [128 n][36w] Wlin chunk
    float* Fs = smem;                         // phase2: [64][132] feats
    float* Wc = smem + 8448;                  // [9][128]
    float* bc = smem + 9600;                  // [9]

    for (int i = tid; i < KK * DLIN; i += 256) Wc[i] = Wcls[i];
    if (tid < KK) bc[tid] = bcls[tid];

    int n0w = w * 16;
    float acc[8][4];
    #pragma unroll
    for (int nt = 0; nt < 8; ++nt)
        #pragma unroll
        for (int j = 0; j < 4; ++j) acc[nt][j] = 0.f;

    const size_t HB = (size_t)BB * HH;
    const __nv_bfloat16* hf = g_h16 + (size_t)(t + 1) * HB + (size_t)(bh * 64) * HH;
    const __nv_bfloat16* hb = g_h16 + (size_t)(TT + 1) * HB + (size_t)t * HB
                                    + (size_t)(bh * 64) * HH;

    int wrow = tid >> 1, wpart = tid & 1;
    int hrow0 = tid >> 3, hc8 = tid & 7;

    for (int kc = 0; kc < 8; ++kc) {
        __syncthreads();
        int kbase = (kc & 3) * 64;
        const __nv_bfloat16* hsrc = (kc < 4) ? hf : hb;
        #pragma unroll
        for (int i = 0; i < 2; ++i) {
            int row = hrow0 + 32 * i;
            uint4 hv = *(const uint4*)(hsrc + (size_t)row * HH + kbase + hc8 * 8);
            *(uint4*)&hsW[row * 36 + hc8 * 4] = hv;
        }
        int kglob = kc * 64;
        #pragma unroll
        for (int j = 0; j < 8; ++j) {
            float4 vv = *(const float4*)&Wlin[(size_t)wrow * 512 + kglob + wpart * 32 + j * 4];
            unsigned w0 = pk2(vv.x, vv.y);
            unsigned w1 = pk2(vv.z, vv.w);
            *(uint2*)&Ws2[wrow * 36 + wpart * 16 + j * 2] = make_uint2(w0, w1);
        }
        __syncthreads();
        #pragma unroll
        for (int kk = 0; kk < 4; ++kk) {
            unsigned a[4];
            int ab = (n0w + q) * 36 + kk * 8 + tg;
            a[0] = Ws2[ab];
            a[1] = Ws2[ab + 8 * 36];
            a[2] = Ws2[ab + 4];
            a[3] = Ws2[ab + 8 * 36 + 4];
            #pragma unroll
            for (int nt = 0; nt < 8; ++nt) {
                int bbse = (nt * 8 + q) * 36 + kk * 8 + tg;
                mma16(acc[nt], a, hsW[bbse], hsW[bbse + 4]);
            }
        }
    }
    __syncthreads();

    float blA = blin[n0w + q], blB = blin[n0w + q + 8];
    #pragma unroll
    for (int nt = 0; nt < 8; ++nt) {
        int b = nt * 8 + 2 * tg;
        float v0 = acc[nt][0] + blA;
        float v1 = acc[nt][1] + blA;
        float v2 = acc[nt][2] + blB;
        float v3 = acc[nt][3] + blB;
        v0 = (v0 > 0.f) ? v0 : expm1f(v0);
        v1 = (v1 > 0.f) ? v1 : expm1f(v1);
        v2 = (v2 > 0.f) ? v2 : expm1f(v2);
        v3 = (v3 > 0.f) ? v3 : expm1f(v3);
        Fs[b * 132 + n0w + q] = v0;
        Fs[(b + 1) * 132 + n0w + q] = v1;
        Fs[b * 132 + n0w + q + 8] = v2;
        Fs[(b + 1) * 132 + n0w + q + 8] = v3;
    }
    __syncthreads();

    for (int p = tid; p < 64 * KK; p += 256) {
        int b = p / KK, k9 = p % KK;
        const float4* fr = (const float4*)&Fs[b * 132];
        const float4* wr = (const float4*)&Wc[k9 * 128];
        float s = 0.f;
        #pragma unroll
        for (int i = 0; i < 32; ++i) {
            float4 f = fr[i], ww = wr[i];
            s += f.x * ww.x + f.y * ww.y + f.z * ww.z + f.w * ww.w;
        }
        int bg = bh * 64 + b;
        g_em[((size_t)bg * TT + t) * KK + k9] = s + bc[k9];
    }
}

// ---------------- kernel 4: CRF NLL --------------------------------------
__global__ void k_crf(const int* __restrict__ labels,
                      const float* __restrict__ start_t,
                      const float* __restrict__ end_t,
                      const float* __restrict__ trans,
                      float* out)
{
    int b = blockIdx.x;
    int j = threadIdx.x;
    const float* em = g_em + (size_t)b * TT * KK;
    int jj = (j < KK) ? j : 0;
    float tr[KK];
    #pragma unroll
    for (int i = 0; i < KK; ++i) tr[i] = trans[i * KK + jj];

    float alpha = (j < KK) ? (start_t[j] + em[j]) : -1e30f;
    for (int t = 1; t < TT; ++t) {
        float e = (j < KK) ? em[t * KK + j] : 0.f;
        float v[KK];
        float m = -1e30f;
        #pragma unroll
        for (int i = 0; i < KK; ++i) {
            float ai = __shfl_sync(0xffffffffu, alpha, i);
            v[i] = ai + tr[i];
            m = fmaxf(m, v[i]);
        }
        float s = 0.f;
        #pragma unroll
        for (int i = 0; i < KK; ++i) s += expf(v[i] - m);
        float na = m + logf(s) + e;
        alpha = (j < KK) ? na : -1e30f;
    }
    float z = (j < KK) ? (alpha + end_t[j]) : -1e30f;
    float m = z;
    #pragma unroll
    for (int o = 16; o > 0; o >>= 1) m = fmaxf(m, __shfl_xor_sync(0xffffffffu, m, o));
    float s = (j < KK) ? expf(z - m) : 0.f;
    #pragma unroll
    for (int o = 16; o > 0; o >>= 1) s += __shfl_xor_sync(0xffffffffu, s, o);
    float logZ = m + logf(s);

    const int* lb = labels + (size_t)b * TT;
    float part = 0.f;
    for (int t = 1 + j; t < TT; t += 32) {
        int lp = lb[t - 1], lc = lb[t];
        part += trans[lp * KK + lc] + em[t * KK + lc];
    }
    #pragma unroll
    for (int o = 16; o > 0; o >>= 1) part += __shfl_xor_sync(0xffffffffu, part, o);

    if (j == 0) {
        int l0 = lb[0];
        float num = part + start_t[l0] + em[l0] + end_t[lb[TT - 1]];
        atomicAdd(out, logZ - num);
    }
}

// ---------------- host launcher ------------------------------------------
extern "C" void kernel_launch(void* const* d_in, const int* in_sizes, int n_in,
                              void* d_out, int out_size) {
    const float* x      = (const float*)d_in[0];
    const int*   labels = (const int*)d_in[2];
    const float* Wih_f  = (const float*)d_in[4];
    const float* Whh_f  = (const float*)d_in[5];
    const float* b_f    = (const float*)d_in[6];
    const float* Wih_b  = (const float*)d_in[7];
    const float* Whh_b  = (const float*)d_in[8];
    const float* b_b    = (const float*)d_in[9];
    const float* Wlin   = (const float*)d_in[10];
    const float* blin   = (const float*)d_in[11];
    const float* Wcls   = (const float*)d_in[12];
    const float* bcls   = (const float*)d_in[13];
    const float* start_t= (const float*)d_in[14];
    const float* end_t  = (const float*)d_in[15];
    const float* trans  = (const float*)d_in[16];
    float* out = (float*)d_out;

    k_zero<<<64, 256>>>(out);
    k_proj<<<16384, 256>>>(x, Wih_f, b_f, Wih_b, b_b);
    k_rnn<<<128, 256>>>(Whh_f, Whh_b);
    k_feats<<<1024, 256>>>(Wlin, blin, Wcls, bcls);
    k_crf<<<128, 32>>>(labels, start_t, end_t, trans, out);
}